// round 14
// baseline (speedup 1.0000x reference)
#include <cuda_runtime.h>
#include <cuda_fp16.h>
#include <cstdint>

#define N_WRD  2000
#define B_SZ   64
#define CSZ    128
#define V_PIX  256
#define EMB    32

// ---------------- scratch (device globals; no allocations allowed) ----------
__device__ float    g_wcode[B_SZ * 6000 + 192];            // padded for tile overrun
__device__ uint32_t g_w2f16[16 * 32 * 64];                 // W2 fp16 B-frags [k16][n8][64]
__device__ uint32_t g_we2f16[16 * 8 * 64];                 // We2 fp16 B-frags [k16][j8][64]
__device__ uint32_t g_vsf16[2 * 32 * 64];                  // vs fp16 B-frags [e16][v8][64]
__device__ uint32_t g_vcf16[(size_t)B_SZ * 16 * 8 * 128];  // VC fp16 A-frags [b][v16][c16][128]
__device__ float4   g_f1p[256];                            // fc1 frag-packed [k16][tg][kq]

// ============================ helpers =======================================
__device__ __forceinline__ uint32_t pack_h2(float lo, float hi) {
    __half2 h = __floats2half2_rn(lo, hi);
    return *(uint32_t*)&h;
}
__device__ __forceinline__ void mma16(float* d, const uint32_t* a, const uint32_t* b) {
    asm volatile("mma.sync.aligned.m16n8k16.row.col.f32.f16.f16.f32 "
        "{%0,%1,%2,%3}, {%4,%5,%6,%7}, {%8,%9}, {%0,%1,%2,%3};"
        : "+f"(d[0]), "+f"(d[1]), "+f"(d[2]), "+f"(d[3])
        : "r"(a[0]), "r"(a[1]), "r"(a[2]), "r"(a[3]), "r"(b[0]), "r"(b[1]));
}
__device__ __forceinline__ void ldm_x4(uint32_t* r, uint32_t addr) {
    asm volatile("ldmatrix.sync.aligned.m8n8.x4.shared.b16 {%0,%1,%2,%3}, [%4];"
        : "=r"(r[0]), "=r"(r[1]), "=r"(r[2]), "=r"(r[3]) : "r"(addr));
}
__device__ __forceinline__ uint32_t ex2_h2(uint32_t x) {
    uint32_t r;
    asm("ex2.approx.f16x2 %0, %1;" : "=r"(r) : "r"(x));
    return r;
}
__device__ __forceinline__ uint32_t smem_u32(const void* p) {
    uint32_t a;
    asm("{ .reg .u64 t; cvta.to.shared.u64 t, %1; cvt.u32.u64 %0, t; }"
        : "=r"(a) : "l"(p));
    return a;
}
__device__ __forceinline__ float sigmoidf_(float x) {
    return 1.f / (1.f + __expf(-x));
}
__device__ __forceinline__ float dot3(const float* wc, float4 q) {
    return fmaf(wc[0], q.x, fmaf(wc[1], q.y, fmaf(wc[2], q.z, q.w)));
}

// ====== setup kernel ========================================================
// blocks: [0,128) w2f16 | [128,160) we2f16 | [160,176) vsf16 | [176,1200) vcf16
//         [1200,1388) wcode (32-col tiles) | [1388] f1p
__global__ __launch_bounds__(256) void k_setup(
    const float* __restrict__ fc2_w, const float* __restrict__ fce_w,
    const float* __restrict__ fca_w, const float* __restrict__ vc_g,
    const float* __restrict__ v, const float* __restrict__ w2c_w1,
    const float* __restrict__ w2c_b1,
    const float* __restrict__ w2c_w2, const float* __restrict__ w2c_b2,
    const float* __restrict__ fc1_w, const float* __restrict__ fc1_b,
    const float* __restrict__ vse_w1, const float* __restrict__ vse_b1,
    const float* __restrict__ vse_w2, const float* __restrict__ vse_b2) {
    const int bid = blockIdx.x;
    const int t = threadIdx.x;
    if (bid < 128) {
        int idx = bid * 256 + t;
        int k16 = idx >> 11, rem = idx & 2047;
        int n8 = rem >> 6, w = rem & 63;
        int lane = w >> 1, h = w & 1;
        int k0 = k16 * 16 + (lane & 3) * 2 + h * 8;
        int n  = n8 * 8 + (lane >> 2);
        g_w2f16[idx] = pack_h2(fc2_w[k0 * 256 + n], fc2_w[(k0 + 1) * 256 + n]);
    } else if (bid < 160) {
        int idx = (bid - 128) * 256 + t;
        int k16 = idx >> 9, rem = idx & 511;
        int j8 = rem >> 6, w = rem & 63;
        int lane = w >> 1, h = w & 1;
        int k0 = k16 * 16 + (lane & 3) * 2 + h * 8;
        int j = j8 * 8 + (lane >> 2);
        float v0 = (j < 32) ? fce_w[k0 * 32 + j] : ((j == 32) ? fca_w[k0] : 0.f);
        float v1 = (j < 32) ? fce_w[(k0 + 1) * 32 + j] : ((j == 32) ? fca_w[k0 + 1] : 0.f);
        g_we2f16[idx] = pack_h2(v0, v1);
    } else if (bid < 176) {
        int idx = (bid - 160) * 256 + t;
        int e16 = idx >> 11, rem = idx & 2047;
        int v8 = rem >> 6, w = rem & 63;
        int lane = w >> 1, h = w & 1;
        int vv = v8 * 8 + (lane >> 2);
        int e0 = e16 * 16 + (lane & 3) * 2 + h * 8;
        float x = -1.f + (2.f / 15.f) * (float)(vv >> 4);
        float y = -1.f + (2.f / 15.f) * (float)(vv & 15);
        float a0 = vse_b2[e0], a1 = vse_b2[e0 + 1];
#pragma unroll 4
        for (int j = 0; j < 128; j++) {
            float hh = fmaxf(fmaf(x, vse_w1[j], fmaf(y, vse_w1[128 + j], vse_b1[j])), 0.f);
            a0 = fmaf(hh, vse_w2[j * EMB + e0], a0);
            a1 = fmaf(hh, vse_w2[j * EMB + e0 + 1], a1);
        }
        g_vsf16[idx] = pack_h2(a0, a1);
    } else if (bid < 1200) {
        int blk = bid - 176;
        int b = blk >> 4, v16 = blk & 15;
        for (int i = t; i < 1024; i += 256) {
            int c16 = i >> 7, w = i & 127;
            int lane = w >> 2, q = w & 3;
            int c = c16 * 16 + (lane >> 2) + (q & 1) * 8;
            int v0 = v16 * 16 + 2 * (lane & 3) + (q >> 1) * 8;
            const float* src = &vc_g[((size_t)b * CSZ + c) * V_PIX + v0];
            g_vcf16[((size_t)(b * 16 + v16) * 8 + c16) * 128 + w] =
                pack_h2(src[0], src[1]);
        }
    } else if (bid < 1388) {
        // ---- wcode tile: 32 cols of 6000, h0 recomputed per k-chunk --------
        __shared__ float As[64 * 33];
        __shared__ float Bs[32 * 36];
        __shared__ float vS[448];
        int tx = t & 7, ty = t >> 3;       // tx: 4 cols, ty: 2 rows
        int n0 = (bid - 1200) * 32;
        for (int i = t; i < 448; i += 256) vS[i] = v[i];
        __syncthreads();
        float acc[2][4] = {};
        for (int k0 = 0; k0 < 512; k0 += 32) {
            for (int i = t; i < 2048; i += 256) {
                int r = i >> 5, k = i & 31;
                int kk = k0 + k;
                float a = w2c_b1[kk];
#pragma unroll
                for (int q = 0; q < 7; q++)
                    a = fmaf(vS[r * 7 + q], w2c_w1[q * 512 + kk], a);
                As[r * 33 + k] = fmaxf(a, 0.f);
            }
            for (int i = t; i < 1024; i += 256) {
                int k = i >> 5, n = i & 31;
                int nn = n0 + n;
                Bs[k * 36 + n] = (nn < 6000) ? w2c_w2[(k0 + k) * 6000 + nn] : 0.f;
            }
            __syncthreads();
#pragma unroll
            for (int k = 0; k < 32; k++) {
                float a[2], bb[4];
#pragma unroll
                for (int i = 0; i < 2; i++) a[i] = As[(2 * ty + i) * 33 + k];
#pragma unroll
                for (int j = 0; j < 4; j++) bb[j] = Bs[k * 36 + 4 * tx + j];
#pragma unroll
                for (int i = 0; i < 2; i++)
#pragma unroll
                    for (int j = 0; j < 4; j++) acc[i][j] = fmaf(a[i], bb[j], acc[i][j]);
            }
            __syncthreads();
        }
#pragma unroll
        for (int i = 0; i < 2; i++) {
            int r = 2 * ty + i;
#pragma unroll
            for (int j = 0; j < 4; j++) {
                int col = n0 + 4 * tx + j;
                if (col < 6000) g_wcode[r * 6000 + col] = acc[i][j] + w2c_b2[col];
            }
        }
    } else {
        // f1p: [k16][tg][kq] -> (fc1_w[k], fc1_w[256+k], fc1_w[512+k], fc1_b[k])
        int k16 = t >> 4, tg = (t >> 2) & 3, kq = t & 3;
        int k = k16 * 16 + 2 * tg + (kq & 1) + (kq >> 1) * 8;
        float4 q;
        q.x = fc1_w[k]; q.y = fc1_w[256 + k]; q.z = fc1_w[512 + k]; q.w = fc1_b[k];
        g_f1p[t] = q;
    }
}

// ====== fused kernel ========================================================
// smem words: As region [0,8448): H2 fp16 [64][264 halves], es fp16 [64][40h],
//             route fp16 [64][264 halves] (phase-disjoint)
#define KF_AS    0
#define KF_ACT   8448       // 64
#define KF_RM    8512       // 256
#define KF_RS    8768       // 256
#define KF_SC    9024       // 64  (per-n scale = act/sum)
#define KF_FC2B  9088       // 256
#define KF_FCEB  9344       // 32
#define KF_WC    9376       // 192
#define KF_TOT   9568       // -> 38272 bytes

__global__ __launch_bounds__(256, 2) void k_AB(
    const float* __restrict__ fc2_b,
    const float* __restrict__ fca_b, const float* __restrict__ fce_b,
    float* __restrict__ out) {
    extern __shared__ float sm[];
    uint32_t* AsU  = (uint32_t*)sm;
    float*    actS = sm + KF_ACT;
    float*    redm = sm + KF_RM;
    float*    reds = sm + KF_RS;
    float*    scS  = sm + KF_SC;
    float*    fc2bS= sm + KF_FC2B;
    float*    fcebS= sm + KF_FCEB;
    float*    wcS  = sm + KF_WC;

    const uint32_t as_b = smem_u32(sm);

    const int t = threadIdx.x;
    const int wid = t >> 5, lane = t & 31;
    const int gr = lane >> 2, tg = lane & 3;
    const int lr8 = (lane >> 3) & 1, l7 = lane & 7, lhi = lane >> 4;
    const int n0g = blockIdx.x * 64;
    const int b   = blockIdx.y;
    const int row0g = b * N_WRD + n0g;

    // ---- consts + wcode rows ----
    fc2bS[t] = fc2_b[t];
    if (t < 32) fcebS[t] = fce_b[t];
    if (t < 192) wcS[t] = g_wcode[row0g * 3 + t];
    __syncthreads();

    // ---- MMA1 (fp16): H2raw = A @ W2 (64x256, K=256). warps 2m x 4n --------
    const int wm = wid & 1, wn = wid >> 1;
    const int m0 = wm * 32, n0 = wn * 64;
    {
        float wcr[4][3];
#pragma unroll
        for (int rr = 0; rr < 4; rr++) {
            int r = m0 + gr + rr * 8;
            wcr[rr][0] = wcS[r * 3 + 0];
            wcr[rr][1] = wcS[r * 3 + 1];
            wcr[rr][2] = wcS[r * 3 + 2];
        }
        const uint32_t* w2p = g_w2f16 + (wn * 8) * 64 + lane * 2;
        const float4* f1t = g_f1p + tg * 4;
        float acc1[2][8][4] = {};
        for (int k16 = 0; k16 < 16; k16++) {
            uint2 curB[8];
            const uint32_t* p = w2p + k16 * 2048;
#pragma unroll
            for (int j = 0; j < 8; j++) curB[j] = *(const uint2*)(p + j * 64);
            const float4* fp = f1t + k16 * 16;
            float4 q0 = fp[0], q1 = fp[1], q2 = fp[2], q3 = fp[3];
            uint32_t aF[2][4];
#pragma unroll
            for (int mt = 0; mt < 2; mt++) {
                const float* w0 = wcr[2 * mt];
                const float* w1 = wcr[2 * mt + 1];
                aF[mt][0] = pack_h2(fmaxf(dot3(w0, q0), 0.f), fmaxf(dot3(w0, q1), 0.f));
                aF[mt][1] = pack_h2(fmaxf(dot3(w1, q0), 0.f), fmaxf(dot3(w1, q1), 0.f));
                aF[mt][2] = pack_h2(fmaxf(dot3(w0, q2), 0.f), fmaxf(dot3(w0, q3), 0.f));
                aF[mt][3] = pack_h2(fmaxf(dot3(w1, q2), 0.f), fmaxf(dot3(w1, q3), 0.f));
            }
#pragma unroll
            for (int j = 0; j < 8; j++)
#pragma unroll
                for (int mt = 0; mt < 2; mt++)
                    mma16(acc1[mt][j], aF[mt], (const uint32_t*)&curB[j]);
        }
        // epilogue1: H2 = relu(acc + bias) -> As fp16 [64][264 halves]
#pragma unroll
        for (int mt = 0; mt < 2; mt++) {
#pragma unroll
            for (int nt = 0; nt < 8; nt++) {
                int col = n0 + nt * 8 + 2 * tg;
                int r0 = m0 + mt * 16 + gr;
                float b0 = fc2bS[col], b1 = fc2bS[col + 1];
                float* d = acc1[mt][nt];
                AsU[r0 * 132 + (col >> 1)] =
                    pack_h2(fmaxf(d[0] + b0, 0.f), fmaxf(d[1] + b1, 0.f));
                AsU[(r0 + 8) * 132 + (col >> 1)] =
                    pack_h2(fmaxf(d[2] + b0, 0.f), fmaxf(d[3] + b1, 0.f));
            }
        }
    }
    __syncthreads();

    // ---- MMA2 (fp16): D2 = H2 @ We2 (64x64, K=256) -------------------------
    const int j0 = wn * 16;
    float acc2[2][2][4] = {};
    {
        const uint32_t* wep = g_we2f16 + (wn * 2) * 64 + lane * 2;
        uint2 curW[2], nxtW[2];
#pragma unroll
        for (int jj = 0; jj < 2; jj++) curW[jj] = *(const uint2*)(wep + jj * 64);
        for (int k16 = 0; k16 < 16; k16++) {
            if (k16 < 15) {
                const uint32_t* p = wep + (k16 + 1) * 512;
#pragma unroll
                for (int jj = 0; jj < 2; jj++) nxtW[jj] = *(const uint2*)(p + jj * 64);
            }
            uint32_t aF[2][4];
#pragma unroll
            for (int mt = 0; mt < 2; mt++) {
                uint32_t adr = as_b + (uint32_t)((m0 + mt * 16 + lr8 * 8 + l7) * 528
                                                  + k16 * 32 + lhi * 16);
                ldm_x4(aF[mt], adr);
            }
#pragma unroll
            for (int jj = 0; jj < 2; jj++)
#pragma unroll
                for (int mt = 0; mt < 2; mt++)
                    mma16(acc2[mt][jj], aF[mt], (const uint32_t*)&curW[jj]);
#pragma unroll
            for (int jj = 0; jj < 2; jj++) curW[jj] = nxtW[jj];
        }
    }
    __syncthreads();   // H2 reads done; As region reused for es

    // ---- epilogue2: es fp16 ([64][40 halves], word stride 20) + act --------
    {
        const float fcab = fca_b[0];
#pragma unroll
        for (int mt = 0; mt < 2; mt++) {
            int r0 = m0 + mt * 16 + gr;
#pragma unroll
            for (int jj = 0; jj < 2; jj++) {
                int col = j0 + jj * 8 + 2 * tg;
                float* d = acc2[mt][jj];
                if (col < 32) {
                    float b0 = fcebS[col], b1 = fcebS[col + 1];
                    AsU[r0 * 20 + (col >> 1)]       = pack_h2(d[0] + b0, d[1] + b1);
                    AsU[(r0 + 8) * 20 + (col >> 1)] = pack_h2(d[2] + b0, d[3] + b1);
                } else if (col == 32) {
                    actS[r0]     = sigmoidf_(d[0] + fcab);
                    actS[r0 + 8] = sigmoidf_(d[2] + fcab);
                }
            }
        }
    }
    __syncthreads();

    // ---- relation (fp16): M=64 n, N=256 v, K=32 ----------------------------
    const int v0 = wn * 64;
    float accr[2][8][4] = {};
    {
        const uint32_t* vsp = g_vsf16 + (wn * 8) * 64 + lane * 2;
        uint2 curV[8], nxtV[8];
#pragma unroll
        for (int j = 0; j < 8; j++) curV[j] = *(const uint2*)(vsp + j * 64);
#pragma unroll
        for (int e16 = 0; e16 < 2; e16++) {
            if (e16 < 1) {
                const uint32_t* p = vsp + 2048;
#pragma unroll
                for (int j = 0; j < 8; j++) nxtV[j] = *(const uint2*)(p + j * 64);
            }
            uint32_t aF[2][4];
#pragma unroll
            for (int mt = 0; mt < 2; mt++) {
                uint32_t adr = as_b + (uint32_t)((m0 + mt * 16 + lr8 * 8 + l7) * 80
                                                  + e16 * 32 + lhi * 16);
                ldm_x4(aF[mt], adr);
            }
#pragma unroll
            for (int j = 0; j < 8; j++)
#pragma unroll
                for (int mt = 0; mt < 2; mt++)
                    mma16(accr[mt][j], aF[mt], (const uint32_t*)&curV[j]);
#pragma unroll
            for (int j = 0; j < 8; j++) curV[j] = nxtV[j];
        }
    }

    // ---- softmax: fp32 max, f16x2 exp, mma row-sums, deferred scaling ------
#pragma unroll
    for (int mt = 0; mt < 2; mt++) {
        float mxa = -1e30f, mxb = -1e30f;
#pragma unroll
        for (int nt = 0; nt < 8; nt++) {
            float* d = accr[mt][nt];
            mxa = fmaxf(mxa, fmaxf(d[0], d[1]));
            mxb = fmaxf(mxb, fmaxf(d[2], d[3]));
        }
        mxa = fmaxf(mxa, __shfl_xor_sync(0xffffffffu, mxa, 1));
        mxa = fmaxf(mxa, __shfl_xor_sync(0xffffffffu, mxa, 2));
        mxb = fmaxf(mxb, __shfl_xor_sync(0xffffffffu, mxb, 1));
        mxb = fmaxf(mxb, __shfl_xor_sync(0xffffffffu, mxb, 2));
        if (tg == 0) {
            redm[(m0 + mt * 16 + gr) * 4 + wn] = mxa;
            redm[(m0 + mt * 16 + 8 + gr) * 4 + wn] = mxb;
        }
    }
    __syncthreads();   // all relation reads of es complete; redm visible

    const float L2E = 1.44269504f;
    const uint32_t ones2[2] = {0x3C003C00u, 0x3C003C00u};
#pragma unroll
    for (int mt = 0; mt < 2; mt++) {
        int na = m0 + mt * 16 + gr, nb = na + 8;
        float ma = fmaxf(fmaxf(redm[na * 4 + 0], redm[na * 4 + 1]),
                         fmaxf(redm[na * 4 + 2], redm[na * 4 + 3]));
        float mb = fmaxf(fmaxf(redm[nb * 4 + 0], redm[nb * 4 + 1]),
                         fmaxf(redm[nb * 4 + 2], redm[nb * 4 + 3]));
        uint32_t Ea[8], Eb[8];
#pragma unroll
        for (int nt = 0; nt < 8; nt++) {
            float* d = accr[mt][nt];
            Ea[nt] = ex2_h2(pack_h2((d[0] - ma) * L2E, (d[1] - ma) * L2E));
            Eb[nt] = ex2_h2(pack_h2((d[2] - mb) * L2E, (d[3] - mb) * L2E));
        }
        // row sums via mma (fp32 accumulate of fp16 exps)
        float sacc[4] = {};
#pragma unroll
        for (int q = 0; q < 4; q++) {
            uint32_t aF[4] = {Ea[2 * q], Eb[2 * q], Ea[2 * q + 1], Eb[2 * q + 1]};
            mma16(sacc, aF, ones2);
        }
        if (tg == 0) { reds[na * 4 + wn] = sacc[0]; reds[nb * 4 + wn] = sacc[2]; }
        // store UNSCALED exp route fp16 [64 n][264 halves] (word stride 132)
#pragma unroll
        for (int nt = 0; nt < 8; nt++) {
            int v = v0 + nt * 8 + 2 * tg;
            AsU[na * 132 + (v >> 1)] = Ea[nt];
            AsU[nb * 132 + (v >> 1)] = Eb[nt];
        }
    }
    __syncthreads();

    // per-n scale = act / sum
    if (t < 64) {
        float s = reds[t * 4] + reds[t * 4 + 1] + reds[t * 4 + 2] + reds[t * 4 + 3];
        scS[t] = actS[t] / s;
    }
    __syncthreads();

    // ---- out GEMM (fp16): out[c][n] = VC @ route, M=128, N=64, K=256 -------
    const int wm2 = wid >> 1, wn2 = wid & 1;
    const int c0 = wm2 * 32, n0o = wn2 * 32;
    float acco[2][4][4] = {};
    {
        const uint32_t* vcp = g_vcf16 + ((size_t)(b * 16) * 8 + wm2 * 2) * 128 + lane * 4;
        uint4 curA[2], nxtA[2];
#pragma unroll
        for (int mt = 0; mt < 2; mt++) curA[mt] = *(const uint4*)(vcp + mt * 128);
        for (int v16 = 0; v16 < 16; v16++) {
            if (v16 < 15) {
                const uint32_t* p = vcp + (size_t)(v16 + 1) * 1024;
#pragma unroll
                for (int mt = 0; mt < 2; mt++) nxtA[mt] = *(const uint4*)(p + mt * 128);
            }
#pragma unroll
            for (int ntp = 0; ntp < 2; ntp++) {
                uint32_t bF[4];
                uint32_t adr = as_b + (uint32_t)((n0o + ntp * 16 + lhi * 8 + l7) * 528
                                                  + v16 * 32 + lr8 * 16);
                ldm_x4(bF, adr);
#pragma unroll
                for (int mt = 0; mt < 2; mt++) {
                    mma16(acco[mt][2 * ntp],     (const uint32_t*)&curA[mt], bF);
                    mma16(acco[mt][2 * ntp + 1], (const uint32_t*)&curA[mt], bF + 2);
                }
            }
#pragma unroll
            for (int mt = 0; mt < 2; mt++) curA[mt] = nxtA[mt];
        }
    }

    // ---- store out with deferred softmax scaling ---------------------------
#pragma unroll
    for (int mt = 0; mt < 2; mt++) {
#pragma unroll
        for (int nt = 0; nt < 4; nt++) {
            int r0 = c0 + mt * 16 + gr;
            int ln = n0o + (nt >> 1) * 16 + (nt & 1) * 8 + 2 * tg;
            int ng = n0g + ln;
            float sc0 = scS[ln], sc1 = scS[ln + 1];
            float* d = acco[mt][nt];
            if (ng < N_WRD) {
                float2 s0; s0.x = d[0] * sc0; s0.y = d[1] * sc1;
                float2 s1; s1.x = d[2] * sc0; s1.y = d[3] * sc1;
                *(float2*)&out[((size_t)b * CSZ + r0) * N_WRD + ng]     = s0;
                *(float2*)&out[((size_t)b * CSZ + r0 + 8) * N_WRD + ng] = s1;
            }
        }
    }
}

// ---------------- launch --------------------------------------------------
extern "C" void kernel_launch(void* const* d_in, const int* in_sizes, int n_in,
                              void* d_out, int out_size) {
    const float* view_cell = (const float*)d_in[0];
    const float* v         = (const float*)d_in[1];
    const float* w2c_w1    = (const float*)d_in[2];
    const float* w2c_b1    = (const float*)d_in[3];
    const float* w2c_w2    = (const float*)d_in[4];
    const float* w2c_b2    = (const float*)d_in[5];
    const float* fc1_w     = (const float*)d_in[6];
    const float* fc1_b     = (const float*)d_in[7];
    const float* fc2_w     = (const float*)d_in[8];
    const float* fc2_b     = (const float*)d_in[9];
    const float* fca_w     = (const float*)d_in[10];
    const float* fca_b     = (const float*)d_in[11];
    const float* fce_w     = (const float*)d_in[12];
    const float* fce_b     = (const float*)d_in[13];
    const float* vse_w1    = (const float*)d_in[14];
    const float* vse_b1    = (const float*)d_in[15];
    const float* vse_w2    = (const float*)d_in[16];
    const float* vse_b2    = (const float*)d_in[17];
    float* out = (float*)d_out;

    static bool attr_set = false;
    if (!attr_set) {
        cudaFuncSetAttribute(k_AB, cudaFuncAttributeMaxDynamicSharedMemorySize, KF_TOT * 4);
        attr_set = true;
    }

    k_setup<<<1389, 256>>>(fc2_w, fce_w, fca_w, view_cell, v, w2c_w1, w2c_b1,
                           w2c_w2, w2c_b2, fc1_w, fc1_b,
                           vse_w1, vse_b1, vse_w2, vse_b2);
    dim3 gridF((N_WRD + 63) / 64, B_SZ);
    k_AB<<<gridF, 256, KF_TOT * 4>>>(fc2_b, fca_b, fce_b, out);
}

// round 16
// speedup vs baseline: 1.1262x; 1.1262x over previous
#include <cuda_runtime.h>
#include <cuda_fp16.h>
#include <cstdint>

#define N_WRD  2000
#define B_SZ   64
#define CSZ    128
#define V_PIX  256
#define EMB    32

// ---------------- scratch (device globals; no allocations allowed) ----------
__device__ float    g_wcode[B_SZ * 6000 + 192];            // padded for tile overrun
__device__ uint32_t g_w2f16[16 * 32 * 64];                 // W2 fp16 B-frags [k16][n8][64]
__device__ uint32_t g_we2f16[16 * 8 * 64];                 // We2 fp16 B-frags [k16][j8][64]
__device__ uint32_t g_vsf16[2 * 32 * 64];                  // vs fp16 B-frags [e16][v8][64]
__device__ uint32_t g_vcf16[(size_t)B_SZ * 16 * 8 * 128];  // VC fp16 A-frags [b][v16][c16][128]
__device__ float4   g_f1p[256];                            // fc1 frag-packed [k16][tg][kq]

// ============================ helpers =======================================
__device__ __forceinline__ uint32_t pack_h2(float lo, float hi) {
    __half2 h = __floats2half2_rn(lo, hi);
    return *(uint32_t*)&h;
}
__device__ __forceinline__ void mma16(float* d, const uint32_t* a, const uint32_t* b) {
    asm volatile("mma.sync.aligned.m16n8k16.row.col.f32.f16.f16.f32 "
        "{%0,%1,%2,%3}, {%4,%5,%6,%7}, {%8,%9}, {%0,%1,%2,%3};"
        : "+f"(d[0]), "+f"(d[1]), "+f"(d[2]), "+f"(d[3])
        : "r"(a[0]), "r"(a[1]), "r"(a[2]), "r"(a[3]), "r"(b[0]), "r"(b[1]));
}
__device__ __forceinline__ void ldm_x4(uint32_t* r, uint32_t addr) {
    asm volatile("ldmatrix.sync.aligned.m8n8.x4.shared.b16 {%0,%1,%2,%3}, [%4];"
        : "=r"(r[0]), "=r"(r[1]), "=r"(r[2]), "=r"(r[3]) : "r"(addr));
}
__device__ __forceinline__ uint32_t ex2_h2(uint32_t x) {
    uint32_t r;
    asm("ex2.approx.f16x2 %0, %1;" : "=r"(r) : "r"(x));
    return r;
}
__device__ __forceinline__ uint32_t smem_u32(const void* p) {
    uint32_t a;
    asm("{ .reg .u64 t; cvta.to.shared.u64 t, %1; cvt.u32.u64 %0, t; }"
        : "=r"(a) : "l"(p));
    return a;
}
__device__ __forceinline__ float sigmoidf_(float x) {
    return 1.f / (1.f + __expf(-x));
}
__device__ __forceinline__ float dot3(const float* wc, float4 q) {
    return fmaf(wc[0], q.x, fmaf(wc[1], q.y, fmaf(wc[2], q.z, q.w)));
}

// ====== setup kernel ========================================================
// blocks: [0,128) w2f16 | [128,160) we2f16 | [160,176) vsf16 | [176,1200) vcf16
//         [1200,1294) wcode (64-col tiles) | [1294] f1p
__global__ __launch_bounds__(256) void k_setup(
    const float* __restrict__ fc2_w, const float* __restrict__ fce_w,
    const float* __restrict__ fca_w, const float* __restrict__ vc_g,
    const float* __restrict__ v, const float* __restrict__ w2c_w1,
    const float* __restrict__ w2c_b1,
    const float* __restrict__ w2c_w2, const float* __restrict__ w2c_b2,
    const float* __restrict__ fc1_w, const float* __restrict__ fc1_b,
    const float* __restrict__ vse_w1, const float* __restrict__ vse_b1,
    const float* __restrict__ vse_w2, const float* __restrict__ vse_b2) {
    const int bid = blockIdx.x;
    const int t = threadIdx.x;
    if (bid < 128) {
        int idx = bid * 256 + t;
        int k16 = idx >> 11, rem = idx & 2047;
        int n8 = rem >> 6, w = rem & 63;
        int lane = w >> 1, h = w & 1;
        int k0 = k16 * 16 + (lane & 3) * 2 + h * 8;
        int n  = n8 * 8 + (lane >> 2);
        g_w2f16[idx] = pack_h2(fc2_w[k0 * 256 + n], fc2_w[(k0 + 1) * 256 + n]);
    } else if (bid < 160) {
        int idx = (bid - 128) * 256 + t;
        int k16 = idx >> 9, rem = idx & 511;
        int j8 = rem >> 6, w = rem & 63;
        int lane = w >> 1, h = w & 1;
        int k0 = k16 * 16 + (lane & 3) * 2 + h * 8;
        int j = j8 * 8 + (lane >> 2);
        float v0 = (j < 32) ? fce_w[k0 * 32 + j] : ((j == 32) ? fca_w[k0] : 0.f);
        float v1 = (j < 32) ? fce_w[(k0 + 1) * 32 + j] : ((j == 32) ? fca_w[k0 + 1] : 0.f);
        g_we2f16[idx] = pack_h2(v0, v1);
    } else if (bid < 176) {
        int idx = (bid - 160) * 256 + t;
        int e16 = idx >> 11, rem = idx & 2047;
        int v8 = rem >> 6, w = rem & 63;
        int lane = w >> 1, h = w & 1;
        int vv = v8 * 8 + (lane >> 2);
        int e0 = e16 * 16 + (lane & 3) * 2 + h * 8;
        float x = -1.f + (2.f / 15.f) * (float)(vv >> 4);
        float y = -1.f + (2.f / 15.f) * (float)(vv & 15);
        float a0 = vse_b2[e0], a1 = vse_b2[e0 + 1];
#pragma unroll 4
        for (int j = 0; j < 128; j++) {
            float hh = fmaxf(fmaf(x, vse_w1[j], fmaf(y, vse_w1[128 + j], vse_b1[j])), 0.f);
            a0 = fmaf(hh, vse_w2[j * EMB + e0], a0);
            a1 = fmaf(hh, vse_w2[j * EMB + e0 + 1], a1);
        }
        g_vsf16[idx] = pack_h2(a0, a1);
    } else if (bid < 1200) {
        int blk = bid - 176;
        int b = blk >> 4, v16 = blk & 15;
        for (int i = t; i < 1024; i += 256) {
            int c16 = i >> 7, w = i & 127;
            int lane = w >> 2, q = w & 3;
            int c = c16 * 16 + (lane >> 2) + (q & 1) * 8;
            int v0 = v16 * 16 + 2 * (lane & 3) + (q >> 1) * 8;
            const float* src = &vc_g[((size_t)b * CSZ + c) * V_PIX + v0];
            g_vcf16[((size_t)(b * 16 + v16) * 8 + c16) * 128 + w] =
                pack_h2(src[0], src[1]);
        }
    } else if (bid < 1294) {
        // ---- wcode tile: 64 cols of 6000, recompute h0 on the fly ----
        __shared__ float As[64 * 33];
        __shared__ float Bs[32 * 68];
        __shared__ float vS[448];
        int tx = t & 15, ty = t >> 4;
        int n0 = (bid - 1200) * 64;
        for (int i = t; i < 448; i += 256) vS[i] = v[i];
        __syncthreads();
        float acc[4][4] = {};
        for (int k0 = 0; k0 < 512; k0 += 32) {
            for (int i = t; i < 2048; i += 256) {
                int r = i >> 5, k = i & 31;
                int kk = k0 + k;
                float a = w2c_b1[kk];
#pragma unroll
                for (int q = 0; q < 7; q++)
                    a = fmaf(vS[r * 7 + q], w2c_w1[q * 512 + kk], a);
                As[r * 33 + k] = fmaxf(a, 0.f);
            }
            for (int i = t; i < 2048; i += 256) {
                int k = i >> 6, n = i & 63;
                int nn = n0 + n;
                Bs[k * 68 + n] = (nn < 6000) ? w2c_w2[(k0 + k) * 6000 + nn] : 0.f;
            }
            __syncthreads();
#pragma unroll
            for (int k = 0; k < 32; k++) {
                float a[4], bb[4];
#pragma unroll
                for (int i = 0; i < 4; i++) a[i] = As[(4 * ty + i) * 33 + k];
#pragma unroll
                for (int j = 0; j < 4; j++) bb[j] = Bs[k * 68 + 4 * tx + j];
#pragma unroll
                for (int i = 0; i < 4; i++)
#pragma unroll
                    for (int j = 0; j < 4; j++) acc[i][j] = fmaf(a[i], bb[j], acc[i][j]);
            }
            __syncthreads();
        }
#pragma unroll
        for (int i = 0; i < 4; i++) {
            int r = 4 * ty + i;
#pragma unroll
            for (int j = 0; j < 4; j++) {
                int col = n0 + 4 * tx + j;
                if (col < 6000) g_wcode[r * 6000 + col] = acc[i][j] + w2c_b2[col];
            }
        }
    } else {
        // f1p: [k16][tg][kq] -> (fc1_w[k], fc1_w[256+k], fc1_w[512+k], fc1_b[k])
        int k16 = t >> 4, tg = (t >> 2) & 3, kq = t & 3;
        int k = k16 * 16 + 2 * tg + (kq & 1) + (kq >> 1) * 8;
        float4 q;
        q.x = fc1_w[k]; q.y = fc1_w[256 + k]; q.z = fc1_w[512 + k]; q.w = fc1_b[k];
        g_f1p[t] = q;
    }
}

// ====== fused kernel ========================================================
// smem words: As region [0,8448): H2 fp16 [64][264 halves], es fp16 [64][40h],
//             route fp16 [64][264 halves] (phase-disjoint)
#define KF_AS    0
#define KF_ACT   8448       // 64
#define KF_RM    8512       // 256
#define KF_RS    8768       // 256
#define KF_SC    9024       // 64  (per-n scale = act/sum)
#define KF_FC2B  9088       // 256
#define KF_FCEB  9344       // 32
#define KF_WC    9376       // 192
#define KF_TOT   9568       // -> 38272 bytes

__global__ __launch_bounds__(256, 2) void k_AB(
    const float* __restrict__ fc2_b,
    const float* __restrict__ fca_b, const float* __restrict__ fce_b,
    float* __restrict__ out) {
    extern __shared__ float sm[];
    uint32_t* AsU  = (uint32_t*)sm;
    float*    actS = sm + KF_ACT;
    float*    redm = sm + KF_RM;
    float*    reds = sm + KF_RS;
    float*    scS  = sm + KF_SC;
    float*    fc2bS= sm + KF_FC2B;
    float*    fcebS= sm + KF_FCEB;
    float*    wcS  = sm + KF_WC;

    const uint32_t as_b = smem_u32(sm);

    const int t = threadIdx.x;
    const int wid = t >> 5, lane = t & 31;
    const int gr = lane >> 2, tg = lane & 3;
    const int lr8 = (lane >> 3) & 1, l7 = lane & 7, lhi = lane >> 4;
    const int n0g = blockIdx.x * 64;
    const int b   = blockIdx.y;
    const int row0g = b * N_WRD + n0g;

    // ---- consts + wcode rows ----
    fc2bS[t] = fc2_b[t];
    if (t < 32) fcebS[t] = fce_b[t];
    if (t < 192) wcS[t] = g_wcode[row0g * 3 + t];
    __syncthreads();

    // ---- MMA1 (fp16): H2raw = A @ W2 (64x256, K=256). warps 2m x 4n --------
    const int wm = wid & 1, wn = wid >> 1;
    const int m0 = wm * 32, n0 = wn * 64;
    {
        float wcr[4][3];
#pragma unroll
        for (int rr = 0; rr < 4; rr++) {
            int r = m0 + gr + rr * 8;
            wcr[rr][0] = wcS[r * 3 + 0];
            wcr[rr][1] = wcS[r * 3 + 1];
            wcr[rr][2] = wcS[r * 3 + 2];
        }
        const uint32_t* w2p = g_w2f16 + (wn * 8) * 64 + lane * 2;
        const float4* f1t = g_f1p + tg * 4;
        float acc1[2][8][4] = {};
        for (int k16 = 0; k16 < 16; k16++) {
            uint2 curB[8];
            const uint32_t* p = w2p + k16 * 2048;
#pragma unroll
            for (int j = 0; j < 8; j++) curB[j] = *(const uint2*)(p + j * 64);
            const float4* fp = f1t + k16 * 16;
            float4 q0 = fp[0], q1 = fp[1], q2 = fp[2], q3 = fp[3];
            uint32_t aF[2][4];
#pragma unroll
            for (int mt = 0; mt < 2; mt++) {
                const float* w0 = wcr[2 * mt];
                const float* w1 = wcr[2 * mt + 1];
                aF[mt][0] = pack_h2(fmaxf(dot3(w0, q0), 0.f), fmaxf(dot3(w0, q1), 0.f));
                aF[mt][1] = pack_h2(fmaxf(dot3(w1, q0), 0.f), fmaxf(dot3(w1, q1), 0.f));
                aF[mt][2] = pack_h2(fmaxf(dot3(w0, q2), 0.f), fmaxf(dot3(w0, q3), 0.f));
                aF[mt][3] = pack_h2(fmaxf(dot3(w1, q2), 0.f), fmaxf(dot3(w1, q3), 0.f));
            }
#pragma unroll
            for (int j = 0; j < 8; j++)
#pragma unroll
                for (int mt = 0; mt < 2; mt++)
                    mma16(acc1[mt][j], aF[mt], (const uint32_t*)&curB[j]);
        }
        // epilogue1: H2 = relu(acc + bias) -> As fp16 [64][264 halves]
#pragma unroll
        for (int mt = 0; mt < 2; mt++) {
#pragma unroll
            for (int nt = 0; nt < 8; nt++) {
                int col = n0 + nt * 8 + 2 * tg;
                int r0 = m0 + mt * 16 + gr;
                float b0 = fc2bS[col], b1 = fc2bS[col + 1];
                float* d = acc1[mt][nt];
                AsU[r0 * 132 + (col >> 1)] =
                    pack_h2(fmaxf(d[0] + b0, 0.f), fmaxf(d[1] + b1, 0.f));
                AsU[(r0 + 8) * 132 + (col >> 1)] =
                    pack_h2(fmaxf(d[2] + b0, 0.f), fmaxf(d[3] + b1, 0.f));
            }
        }
    }
    __syncthreads();

    // ---- MMA2 (fp16): D2 = H2 @ We2 (64x64, K=256) -------------------------
    const int j0 = wn * 16;
    float acc2[2][2][4] = {};
    {
        const uint32_t* wep = g_we2f16 + (wn * 2) * 64 + lane * 2;
        uint2 curW[2], nxtW[2];
#pragma unroll
        for (int jj = 0; jj < 2; jj++) curW[jj] = *(const uint2*)(wep + jj * 64);
        for (int k16 = 0; k16 < 16; k16++) {
            if (k16 < 15) {
                const uint32_t* p = wep + (k16 + 1) * 512;
#pragma unroll
                for (int jj = 0; jj < 2; jj++) nxtW[jj] = *(const uint2*)(p + jj * 64);
            }
            uint32_t aF[2][4];
#pragma unroll
            for (int mt = 0; mt < 2; mt++) {
                uint32_t adr = as_b + (uint32_t)((m0 + mt * 16 + lr8 * 8 + l7) * 528
                                                  + k16 * 32 + lhi * 16);
                ldm_x4(aF[mt], adr);
            }
#pragma unroll
            for (int jj = 0; jj < 2; jj++)
#pragma unroll
                for (int mt = 0; mt < 2; mt++)
                    mma16(acc2[mt][jj], aF[mt], (const uint32_t*)&curW[jj]);
#pragma unroll
            for (int jj = 0; jj < 2; jj++) curW[jj] = nxtW[jj];
        }
    }
    __syncthreads();   // H2 reads done; As region reused for es

    // ---- epilogue2: es fp16 ([64][40 halves], word stride 20) + act --------
    {
        const float fcab = fca_b[0];
#pragma unroll
        for (int mt = 0; mt < 2; mt++) {
            int r0 = m0 + mt * 16 + gr;
#pragma unroll
            for (int jj = 0; jj < 2; jj++) {
                int col = j0 + jj * 8 + 2 * tg;
                float* d = acc2[mt][jj];
                if (col < 32) {
                    float b0 = fcebS[col], b1 = fcebS[col + 1];
                    AsU[r0 * 20 + (col >> 1)]       = pack_h2(d[0] + b0, d[1] + b1);
                    AsU[(r0 + 8) * 20 + (col >> 1)] = pack_h2(d[2] + b0, d[3] + b1);
                } else if (col == 32) {
                    actS[r0]     = sigmoidf_(d[0] + fcab);
                    actS[r0 + 8] = sigmoidf_(d[2] + fcab);
                }
            }
        }
    }
    __syncthreads();

    // ---- relation (fp16): M=64 n, N=256 v, K=32 ----------------------------
    const int v0 = wn * 64;
    float accr[2][8][4] = {};
    {
        const uint32_t* vsp = g_vsf16 + (wn * 8) * 64 + lane * 2;
        uint2 curV[8], nxtV[8];
#pragma unroll
        for (int j = 0; j < 8; j++) curV[j] = *(const uint2*)(vsp + j * 64);
#pragma unroll
        for (int e16 = 0; e16 < 2; e16++) {
            if (e16 < 1) {
                const uint32_t* p = vsp + 2048;
#pragma unroll
                for (int j = 0; j < 8; j++) nxtV[j] = *(const uint2*)(p + j * 64);
            }
            uint32_t aF[2][4];
#pragma unroll
            for (int mt = 0; mt < 2; mt++) {
                uint32_t adr = as_b + (uint32_t)((m0 + mt * 16 + lr8 * 8 + l7) * 80
                                                  + e16 * 32 + lhi * 16);
                ldm_x4(aF[mt], adr);
            }
#pragma unroll
            for (int j = 0; j < 8; j++)
#pragma unroll
                for (int mt = 0; mt < 2; mt++)
                    mma16(accr[mt][j], aF[mt], (const uint32_t*)&curV[j]);
#pragma unroll
            for (int j = 0; j < 8; j++) curV[j] = nxtV[j];
        }
    }

    // ---- softmax: fp32 max, f16x2 exp, mma row-sums, deferred scaling ------
#pragma unroll
    for (int mt = 0; mt < 2; mt++) {
        float mxa = -1e30f, mxb = -1e30f;
#pragma unroll
        for (int nt = 0; nt < 8; nt++) {
            float* d = accr[mt][nt];
            mxa = fmaxf(mxa, fmaxf(d[0], d[1]));
            mxb = fmaxf(mxb, fmaxf(d[2], d[3]));
        }
        mxa = fmaxf(mxa, __shfl_xor_sync(0xffffffffu, mxa, 1));
        mxa = fmaxf(mxa, __shfl_xor_sync(0xffffffffu, mxa, 2));
        mxb = fmaxf(mxb, __shfl_xor_sync(0xffffffffu, mxb, 1));
        mxb = fmaxf(mxb, __shfl_xor_sync(0xffffffffu, mxb, 2));
        if (tg == 0) {
            redm[(m0 + mt * 16 + gr) * 4 + wn] = mxa;
            redm[(m0 + mt * 16 + 8 + gr) * 4 + wn] = mxb;
        }
    }
    __syncthreads();   // all relation reads of es complete; redm visible

    const float L2E = 1.44269504f;
    const uint32_t ones2[2] = {0x3C003C00u, 0x3C003C00u};
#pragma unroll
    for (int mt = 0; mt < 2; mt++) {
        int na = m0 + mt * 16 + gr, nb = na + 8;
        float ma = fmaxf(fmaxf(redm[na * 4 + 0], redm[na * 4 + 1]),
                         fmaxf(redm[na * 4 + 2], redm[na * 4 + 3]));
        float mb = fmaxf(fmaxf(redm[nb * 4 + 0], redm[nb * 4 + 1]),
                         fmaxf(redm[nb * 4 + 2], redm[nb * 4 + 3]));
        uint32_t Ea[8], Eb[8];
#pragma unroll
        for (int nt = 0; nt < 8; nt++) {
            float* d = accr[mt][nt];
            Ea[nt] = ex2_h2(pack_h2((d[0] - ma) * L2E, (d[1] - ma) * L2E));
            Eb[nt] = ex2_h2(pack_h2((d[2] - mb) * L2E, (d[3] - mb) * L2E));
        }
        // row sums via mma (fp32 accumulate of fp16 exps)
        float sacc[4] = {};
#pragma unroll
        for (int q = 0; q < 4; q++) {
            uint32_t aF[4] = {Ea[2 * q], Eb[2 * q], Ea[2 * q + 1], Eb[2 * q + 1]};
            mma16(sacc, aF, ones2);
        }
        if (tg == 0) { reds[na * 4 + wn] = sacc[0]; reds[nb * 4 + wn] = sacc[2]; }
        // store UNSCALED exp route fp16 [64 n][264 halves] (word stride 132)
#pragma unroll
        for (int nt = 0; nt < 8; nt++) {
            int v = v0 + nt * 8 + 2 * tg;
            AsU[na * 132 + (v >> 1)] = Ea[nt];
            AsU[nb * 132 + (v >> 1)] = Eb[nt];
        }
    }
    __syncthreads();

    // per-n scale = act / sum
    if (t < 64) {
        float s = reds[t * 4] + reds[t * 4 + 1] + reds[t * 4 + 2] + reds[t * 4 + 3];
        scS[t] = actS[t] / s;
    }
    __syncthreads();

    // ---- out GEMM (fp16): out[c][n] = VC @ route, M=128, N=64, K=256 -------
    const int wm2 = wid >> 1, wn2 = wid & 1;
    const int c0 = wm2 * 32, n0o = wn2 * 32;
    float acco[2][4][4] = {};
    {
        const uint32_t* vcp = g_vcf16 + ((size_t)(b * 16) * 8 + wm2 * 2) * 128 + lane * 4;
        uint4 curA[2], nxtA[2];
#pragma unroll
        for (int mt = 0; mt < 2; mt++) curA[mt] = *(const uint4*)(vcp + mt * 128);
        for (int v16 = 0; v16 < 16; v16++) {
            if (v16 < 15) {
                const uint32_t* p = vcp + (size_t)(v16 + 1) * 1024;
#pragma unroll
                for (int mt = 0; mt < 2; mt++) nxtA[mt] = *(const uint4*)(p + mt * 128);
            }
#pragma unroll
            for (int ntp = 0; ntp < 2; ntp++) {
                uint32_t bF[4];
                uint32_t adr = as_b + (uint32_t)((n0o + ntp * 16 + lhi * 8 + l7) * 528
                                                  + v16 * 32 + lr8 * 16);
                ldm_x4(bF, adr);
#pragma unroll
                for (int mt = 0; mt < 2; mt++) {
                    mma16(acco[mt][2 * ntp],     (const uint32_t*)&curA[mt], bF);
                    mma16(acco[mt][2 * ntp + 1], (const uint32_t*)&curA[mt], bF + 2);
                }
            }
#pragma unroll
            for (int mt = 0; mt < 2; mt++) curA[mt] = nxtA[mt];
        }
    }

    // ---- store out with deferred softmax scaling ---------------------------
#pragma unroll
    for (int mt = 0; mt < 2; mt++) {
#pragma unroll
        for (int nt = 0; nt < 4; nt++) {
            int r0 = c0 + mt * 16 + gr;
            int ln = n0o + (nt >> 1) * 16 + (nt & 1) * 8 + 2 * tg;
            int ng = n0g + ln;
            float sc0 = scS[ln], sc1 = scS[ln + 1];
            float* d = acco[mt][nt];
            if (ng < N_WRD) {
                float2 s0; s0.x = d[0] * sc0; s0.y = d[1] * sc1;
                float2 s1; s1.x = d[2] * sc0; s1.y = d[3] * sc1;
                *(float2*)&out[((size_t)b * CSZ + r0) * N_WRD + ng]     = s0;
                *(float2*)&out[((size_t)b * CSZ + r0 + 8) * N_WRD + ng] = s1;
            }
        }
    }
}

// ---------------- launch --------------------------------------------------
extern "C" void kernel_launch(void* const* d_in, const int* in_sizes, int n_in,
                              void* d_out, int out_size) {
    const float* view_cell = (const float*)d_in[0];
    const float* v         = (const float*)d_in[1];
    const float* w2c_w1    = (const float*)d_in[2];
    const float* w2c_b1    = (const float*)d_in[3];
    const float* w2c_w2    = (const float*)d_in[4];
    const float* w2c_b2    = (const float*)d_in[5];
    const float* fc1_w     = (const float*)d_in[6];
    const float* fc1_b     = (const float*)d_in[7];
    const float* fc2_w     = (const float*)d_in[8];
    const float* fc2_b     = (const float*)d_in[9];
    const float* fca_w     = (const float*)d_in[10];
    const float* fca_b     = (const float*)d_in[11];
    const float* fce_w     = (const float*)d_in[12];
    const float* fce_b     = (const float*)d_in[13];
    const float* vse_w1    = (const float*)d_in[14];
    const float* vse_b1    = (const float*)d_in[15];
    const float* vse_w2    = (const float*)d_in[16];
    const float* vse_b2    = (const float*)d_in[17];
    float* out = (float*)d_out;

    static bool attr_set = false;
    if (!attr_set) {
        cudaFuncSetAttribute(k_AB, cudaFuncAttributeMaxDynamicSharedMemorySize, KF_TOT * 4);
        attr_set = true;
    }

    k_setup<<<1295, 256>>>(fc2_w, fce_w, fca_w, view_cell, v, w2c_w1, w2c_b1,
                           w2c_w2, w2c_b2, fc1_w, fc1_b,
                           vse_w1, vse_b1, vse_w2, vse_b2);
    dim3 gridF((N_WRD + 63) / 64, B_SZ);
    k_AB<<<gridF, 256, KF_TOT * 4>>>(fc2_b, fca_b, fce_b, out);
}

// round 17
// speedup vs baseline: 1.2430x; 1.1038x over previous
#include <cuda_runtime.h>
#include <cuda_fp16.h>
#include <cstdint>

#define N_WRD  2000
#define B_SZ   64
#define CSZ    128
#define V_PIX  256
#define EMB    32

// ---------------- scratch (device globals; no allocations allowed) ----------
__device__ float    g_wcode[B_SZ * 6000 + 192];            // padded for tile overrun
__device__ uint32_t g_w2f16[16 * 32 * 64];                 // W2 fp16 B-frags [k16][n8][64]
__device__ uint32_t g_we2f16[16 * 8 * 64];                 // We2 fp16 B-frags [k16][j8][64]
__device__ uint32_t g_vsf16[2 * 32 * 64];                  // vs fp16 B-frags [e16][v8][64]
__device__ uint32_t g_vcf16[(size_t)B_SZ * 16 * 8 * 128];  // VC fp16 A-frags [b][v16][c16][128]
__device__ float4   g_f1p[256];                            // fc1 frag-packed [k16][tg][kq]

// ============================ helpers =======================================
__device__ __forceinline__ uint32_t pack_h2(float lo, float hi) {
    __half2 h = __floats2half2_rn(lo, hi);
    return *(uint32_t*)&h;
}
__device__ __forceinline__ void mma16(float* d, const uint32_t* a, const uint32_t* b) {
    asm volatile("mma.sync.aligned.m16n8k16.row.col.f32.f16.f16.f32 "
        "{%0,%1,%2,%3}, {%4,%5,%6,%7}, {%8,%9}, {%0,%1,%2,%3};"
        : "+f"(d[0]), "+f"(d[1]), "+f"(d[2]), "+f"(d[3])
        : "r"(a[0]), "r"(a[1]), "r"(a[2]), "r"(a[3]), "r"(b[0]), "r"(b[1]));
}
__device__ __forceinline__ void ldm_x4(uint32_t* r, uint32_t addr) {
    asm volatile("ldmatrix.sync.aligned.m8n8.x4.shared.b16 {%0,%1,%2,%3}, [%4];"
        : "=r"(r[0]), "=r"(r[1]), "=r"(r[2]), "=r"(r[3]) : "r"(addr));
}
__device__ __forceinline__ uint32_t ex2_h2(uint32_t x) {
    uint32_t r;
    asm("ex2.approx.f16x2 %0, %1;" : "=r"(r) : "r"(x));
    return r;
}
__device__ __forceinline__ uint32_t smem_u32(const void* p) {
    uint32_t a;
    asm("{ .reg .u64 t; cvta.to.shared.u64 t, %1; cvt.u32.u64 %0, t; }"
        : "=r"(a) : "l"(p));
    return a;
}
__device__ __forceinline__ float sigmoidf_(float x) {
    return 1.f / (1.f + __expf(-x));
}
__device__ __forceinline__ float dot3(const float* wc, float4 q) {
    return fmaf(wc[0], q.x, fmaf(wc[1], q.y, fmaf(wc[2], q.z, q.w)));
}

// ====== setup kernel ========================================================
// blocks (heavy first): [0,94) wcode | [94,222) w2f16 | [222,254) we2f16
//   | [254,270) vsf16 | [270,782) vcf16 (staged) | [782] f1p
__global__ __launch_bounds__(256) void k_setup(
    const float* __restrict__ fc2_w, const float* __restrict__ fce_w,
    const float* __restrict__ fca_w, const float* __restrict__ vc_g,
    const float* __restrict__ v, const float* __restrict__ w2c_w1,
    const float* __restrict__ w2c_b1,
    const float* __restrict__ w2c_w2, const float* __restrict__ w2c_b2,
    const float* __restrict__ fc1_w, const float* __restrict__ fc1_b,
    const float* __restrict__ vse_w1, const float* __restrict__ vse_b1,
    const float* __restrict__ vse_w2, const float* __restrict__ vse_b2) {
    const int bid = blockIdx.x;
    const int t = threadIdx.x;
    if (bid < 94) {
        // ---- wcode tile: 64 cols of 6000, recompute h0 on the fly ----
        __shared__ float As[64 * 33];
        __shared__ float Bs[32 * 68];
        __shared__ float vS[448];
        int tx = t & 15, ty = t >> 4;
        int n0 = bid * 64;
        for (int i = t; i < 448; i += 256) vS[i] = v[i];
        __syncthreads();
        float acc[4][4] = {};
        for (int k0 = 0; k0 < 512; k0 += 32) {
            for (int i = t; i < 2048; i += 256) {
                int r = i >> 5, k = i & 31;
                int kk = k0 + k;
                float a = w2c_b1[kk];
#pragma unroll
                for (int q = 0; q < 7; q++)
                    a = fmaf(vS[r * 7 + q], w2c_w1[q * 512 + kk], a);
                As[r * 33 + k] = fmaxf(a, 0.f);
            }
            for (int i = t; i < 2048; i += 256) {
                int k = i >> 6, n = i & 63;
                int nn = n0 + n;
                Bs[k * 68 + n] = (nn < 6000) ? w2c_w2[(k0 + k) * 6000 + nn] : 0.f;
            }
            __syncthreads();
#pragma unroll
            for (int k = 0; k < 32; k++) {
                float a[4], bb[4];
#pragma unroll
                for (int i = 0; i < 4; i++) a[i] = As[(4 * ty + i) * 33 + k];
#pragma unroll
                for (int j = 0; j < 4; j++) bb[j] = Bs[k * 68 + 4 * tx + j];
#pragma unroll
                for (int i = 0; i < 4; i++)
#pragma unroll
                    for (int j = 0; j < 4; j++) acc[i][j] = fmaf(a[i], bb[j], acc[i][j]);
            }
            __syncthreads();
        }
#pragma unroll
        for (int i = 0; i < 4; i++) {
            int r = 4 * ty + i;
#pragma unroll
            for (int j = 0; j < 4; j++) {
                int col = n0 + 4 * tx + j;
                if (col < 6000) g_wcode[r * 6000 + col] = acc[i][j] + w2c_b2[col];
            }
        }
    } else if (bid < 222) {
        int idx = (bid - 94) * 256 + t;
        int k16 = idx >> 11, rem = idx & 2047;
        int n8 = rem >> 6, w = rem & 63;
        int lane = w >> 1, h = w & 1;
        int k0 = k16 * 16 + (lane & 3) * 2 + h * 8;
        int n  = n8 * 8 + (lane >> 2);
        g_w2f16[idx] = pack_h2(fc2_w[k0 * 256 + n], fc2_w[(k0 + 1) * 256 + n]);
    } else if (bid < 254) {
        int idx = (bid - 222) * 256 + t;
        int k16 = idx >> 9, rem = idx & 511;
        int j8 = rem >> 6, w = rem & 63;
        int lane = w >> 1, h = w & 1;
        int k0 = k16 * 16 + (lane & 3) * 2 + h * 8;
        int j = j8 * 8 + (lane >> 2);
        float v0 = (j < 32) ? fce_w[k0 * 32 + j] : ((j == 32) ? fca_w[k0] : 0.f);
        float v1 = (j < 32) ? fce_w[(k0 + 1) * 32 + j] : ((j == 32) ? fca_w[k0 + 1] : 0.f);
        g_we2f16[idx] = pack_h2(v0, v1);
    } else if (bid < 270) {
        int idx = (bid - 254) * 256 + t;
        int e16 = idx >> 11, rem = idx & 2047;
        int v8 = rem >> 6, w = rem & 63;
        int lane = w >> 1, h = w & 1;
        int vv = v8 * 8 + (lane >> 2);
        int e0 = e16 * 16 + (lane & 3) * 2 + h * 8;
        float x = -1.f + (2.f / 15.f) * (float)(vv >> 4);
        float y = -1.f + (2.f / 15.f) * (float)(vv & 15);
        float a0 = vse_b2[e0], a1 = vse_b2[e0 + 1];
#pragma unroll 4
        for (int j = 0; j < 128; j++) {
            float hh = fmaxf(fmaf(x, vse_w1[j], fmaf(y, vse_w1[128 + j], vse_b1[j])), 0.f);
            a0 = fmaf(hh, vse_w2[j * EMB + e0], a0);
            a1 = fmaf(hh, vse_w2[j * EMB + e0 + 1], a1);
        }
        g_vsf16[idx] = pack_h2(a0, a1);
    } else if (bid < 782) {
        // ---- VC fp16 A-frags, staged: block = (b, c16); coalesced in+out ---
        __shared__ float vcS[16 * 260];
        int blk = bid - 270;
        int b = blk >> 3, c16 = blk & 7;
        const float* src = vc_g + ((size_t)b * CSZ + c16 * 16) * V_PIX;
#pragma unroll
        for (int i = 0; i < 4; i++) {
            int idx = t + 256 * i;                  // float4 index
            int row = idx >> 6, col4 = (idx & 63) * 4;
            float4 q = *(const float4*)&src[row * 256 + col4];
            *(float4*)&vcS[row * 260 + col4] = q;
        }
        __syncthreads();
        uint32_t* dst = g_vcf16 + ((size_t)(b * 16) * 8 + c16) * 128;
#pragma unroll
        for (int j = 0; j < 8; j++) {
            int idx = t + 256 * j;
            int v16 = idx >> 7, w = idx & 127;
            int lane = w >> 2, q = w & 3;
            int cl = (lane >> 2) + (q & 1) * 8;
            int v0 = v16 * 16 + 2 * (lane & 3) + (q >> 1) * 8;
            dst[(size_t)v16 * 1024 + w] =
                pack_h2(vcS[cl * 260 + v0], vcS[cl * 260 + v0 + 1]);
        }
    } else {
        // f1p: [k16][tg][kq] -> (fc1_w[k], fc1_w[256+k], fc1_w[512+k], fc1_b[k])
        int k16 = t >> 4, tg = (t >> 2) & 3, kq = t & 3;
        int k = k16 * 16 + 2 * tg + (kq & 1) + (kq >> 1) * 8;
        float4 q;
        q.x = fc1_w[k]; q.y = fc1_w[256 + k]; q.z = fc1_w[512 + k]; q.w = fc1_b[k];
        g_f1p[t] = q;
    }
}

// ====== fused kernel (unchanged from R16) ===================================
#define KF_AS    0
#define KF_ACT   8448       // 64
#define KF_RM    8512       // 256
#define KF_RS    8768       // 256
#define KF_SC    9024       // 64  (per-n scale = act/sum)
#define KF_FC2B  9088       // 256
#define KF_FCEB  9344       // 32
#define KF_WC    9376       // 192
#define KF_TOT   9568       // -> 38272 bytes

__global__ __launch_bounds__(256, 2) void k_AB(
    const float* __restrict__ fc2_b,
    const float* __restrict__ fca_b, const float* __restrict__ fce_b,
    float* __restrict__ out) {
    extern __shared__ float sm[];
    uint32_t* AsU  = (uint32_t*)sm;
    float*    actS = sm + KF_ACT;
    float*    redm = sm + KF_RM;
    float*    reds = sm + KF_RS;
    float*    scS  = sm + KF_SC;
    float*    fc2bS= sm + KF_FC2B;
    float*    fcebS= sm + KF_FCEB;
    float*    wcS  = sm + KF_WC;

    const uint32_t as_b = smem_u32(sm);

    const int t = threadIdx.x;
    const int wid = t >> 5, lane = t & 31;
    const int gr = lane >> 2, tg = lane & 3;
    const int lr8 = (lane >> 3) & 1, l7 = lane & 7, lhi = lane >> 4;
    const int n0g = blockIdx.x * 64;
    const int b   = blockIdx.y;
    const int row0g = b * N_WRD + n0g;

    fc2bS[t] = fc2_b[t];
    if (t < 32) fcebS[t] = fce_b[t];
    if (t < 192) wcS[t] = g_wcode[row0g * 3 + t];
    __syncthreads();

    // ---- MMA1 (fp16): H2raw = A @ W2 (64x256, K=256). warps 2m x 4n --------
    const int wm = wid & 1, wn = wid >> 1;
    const int m0 = wm * 32, n0 = wn * 64;
    {
        float wcr[4][3];
#pragma unroll
        for (int rr = 0; rr < 4; rr++) {
            int r = m0 + gr + rr * 8;
            wcr[rr][0] = wcS[r * 3 + 0];
            wcr[rr][1] = wcS[r * 3 + 1];
            wcr[rr][2] = wcS[r * 3 + 2];
        }
        const uint32_t* w2p = g_w2f16 + (wn * 8) * 64 + lane * 2;
        const float4* f1t = g_f1p + tg * 4;
        float acc1[2][8][4] = {};
        for (int k16 = 0; k16 < 16; k16++) {
            uint2 curB[8];
            const uint32_t* p = w2p + k16 * 2048;
#pragma unroll
            for (int j = 0; j < 8; j++) curB[j] = *(const uint2*)(p + j * 64);
            const float4* fp = f1t + k16 * 16;
            float4 q0 = fp[0], q1 = fp[1], q2 = fp[2], q3 = fp[3];
            uint32_t aF[2][4];
#pragma unroll
            for (int mt = 0; mt < 2; mt++) {
                const float* w0 = wcr[2 * mt];
                const float* w1 = wcr[2 * mt + 1];
                aF[mt][0] = pack_h2(fmaxf(dot3(w0, q0), 0.f), fmaxf(dot3(w0, q1), 0.f));
                aF[mt][1] = pack_h2(fmaxf(dot3(w1, q0), 0.f), fmaxf(dot3(w1, q1), 0.f));
                aF[mt][2] = pack_h2(fmaxf(dot3(w0, q2), 0.f), fmaxf(dot3(w0, q3), 0.f));
                aF[mt][3] = pack_h2(fmaxf(dot3(w1, q2), 0.f), fmaxf(dot3(w1, q3), 0.f));
            }
#pragma unroll
            for (int j = 0; j < 8; j++)
#pragma unroll
                for (int mt = 0; mt < 2; mt++)
                    mma16(acc1[mt][j], aF[mt], (const uint32_t*)&curB[j]);
        }
#pragma unroll
        for (int mt = 0; mt < 2; mt++) {
#pragma unroll
            for (int nt = 0; nt < 8; nt++) {
                int col = n0 + nt * 8 + 2 * tg;
                int r0 = m0 + mt * 16 + gr;
                float b0 = fc2bS[col], b1 = fc2bS[col + 1];
                float* d = acc1[mt][nt];
                AsU[r0 * 132 + (col >> 1)] =
                    pack_h2(fmaxf(d[0] + b0, 0.f), fmaxf(d[1] + b1, 0.f));
                AsU[(r0 + 8) * 132 + (col >> 1)] =
                    pack_h2(fmaxf(d[2] + b0, 0.f), fmaxf(d[3] + b1, 0.f));
            }
        }
    }
    __syncthreads();

    // ---- MMA2 (fp16): D2 = H2 @ We2 (64x64, K=256) -------------------------
    const int j0 = wn * 16;
    float acc2[2][2][4] = {};
    {
        const uint32_t* wep = g_we2f16 + (wn * 2) * 64 + lane * 2;
        uint2 curW[2], nxtW[2];
#pragma unroll
        for (int jj = 0; jj < 2; jj++) curW[jj] = *(const uint2*)(wep + jj * 64);
        for (int k16 = 0; k16 < 16; k16++) {
            if (k16 < 15) {
                const uint32_t* p = wep + (k16 + 1) * 512;
#pragma unroll
                for (int jj = 0; jj < 2; jj++) nxtW[jj] = *(const uint2*)(p + jj * 64);
            }
            uint32_t aF[2][4];
#pragma unroll
            for (int mt = 0; mt < 2; mt++) {
                uint32_t adr = as_b + (uint32_t)((m0 + mt * 16 + lr8 * 8 + l7) * 528
                                                  + k16 * 32 + lhi * 16);
                ldm_x4(aF[mt], adr);
            }
#pragma unroll
            for (int jj = 0; jj < 2; jj++)
#pragma unroll
                for (int mt = 0; mt < 2; mt++)
                    mma16(acc2[mt][jj], aF[mt], (const uint32_t*)&curW[jj]);
#pragma unroll
            for (int jj = 0; jj < 2; jj++) curW[jj] = nxtW[jj];
        }
    }
    __syncthreads();

    // ---- epilogue2: es fp16 ([64][40 halves], word stride 20) + act --------
    {
        const float fcab = fca_b[0];
#pragma unroll
        for (int mt = 0; mt < 2; mt++) {
            int r0 = m0 + mt * 16 + gr;
#pragma unroll
            for (int jj = 0; jj < 2; jj++) {
                int col = j0 + jj * 8 + 2 * tg;
                float* d = acc2[mt][jj];
                if (col < 32) {
                    float b0 = fcebS[col], b1 = fcebS[col + 1];
                    AsU[r0 * 20 + (col >> 1)]       = pack_h2(d[0] + b0, d[1] + b1);
                    AsU[(r0 + 8) * 20 + (col >> 1)] = pack_h2(d[2] + b0, d[3] + b1);
                } else if (col == 32) {
                    actS[r0]     = sigmoidf_(d[0] + fcab);
                    actS[r0 + 8] = sigmoidf_(d[2] + fcab);
                }
            }
        }
    }
    __syncthreads();

    // ---- relation (fp16): M=64 n, N=256 v, K=32 ----------------------------
    const int v0 = wn * 64;
    float accr[2][8][4] = {};
    {
        const uint32_t* vsp = g_vsf16 + (wn * 8) * 64 + lane * 2;
        uint2 curV[8], nxtV[8];
#pragma unroll
        for (int j = 0; j < 8; j++) curV[j] = *(const uint2*)(vsp + j * 64);
#pragma unroll
        for (int e16 = 0; e16 < 2; e16++) {
            if (e16 < 1) {
                const uint32_t* p = vsp + 2048;
#pragma unroll
                for (int j = 0; j < 8; j++) nxtV[j] = *(const uint2*)(p + j * 64);
            }
            uint32_t aF[2][4];
#pragma unroll
            for (int mt = 0; mt < 2; mt++) {
                uint32_t adr = as_b + (uint32_t)((m0 + mt * 16 + lr8 * 8 + l7) * 80
                                                  + e16 * 32 + lhi * 16);
                ldm_x4(aF[mt], adr);
            }
#pragma unroll
            for (int j = 0; j < 8; j++)
#pragma unroll
                for (int mt = 0; mt < 2; mt++)
                    mma16(accr[mt][j], aF[mt], (const uint32_t*)&curV[j]);
#pragma unroll
            for (int j = 0; j < 8; j++) curV[j] = nxtV[j];
        }
    }

    // ---- softmax: fp32 max, f16x2 exp, mma row-sums, deferred scaling ------
#pragma unroll
    for (int mt = 0; mt < 2; mt++) {
        float mxa = -1e30f, mxb = -1e30f;
#pragma unroll
        for (int nt = 0; nt < 8; nt++) {
            float* d = accr[mt][nt];
            mxa = fmaxf(mxa, fmaxf(d[0], d[1]));
            mxb = fmaxf(mxb, fmaxf(d[2], d[3]));
        }
        mxa = fmaxf(mxa, __shfl_xor_sync(0xffffffffu, mxa, 1));
        mxa = fmaxf(mxa, __shfl_xor_sync(0xffffffffu, mxa, 2));
        mxb = fmaxf(mxb, __shfl_xor_sync(0xffffffffu, mxb, 1));
        mxb = fmaxf(mxb, __shfl_xor_sync(0xffffffffu, mxb, 2));
        if (tg == 0) {
            redm[(m0 + mt * 16 + gr) * 4 + wn] = mxa;
            redm[(m0 + mt * 16 + 8 + gr) * 4 + wn] = mxb;
        }
    }
    __syncthreads();

    const float L2E = 1.44269504f;
    const uint32_t ones2[2] = {0x3C003C00u, 0x3C003C00u};
#pragma unroll
    for (int mt = 0; mt < 2; mt++) {
        int na = m0 + mt * 16 + gr, nb = na + 8;
        float ma = fmaxf(fmaxf(redm[na * 4 + 0], redm[na * 4 + 1]),
                         fmaxf(redm[na * 4 + 2], redm[na * 4 + 3]));
        float mb = fmaxf(fmaxf(redm[nb * 4 + 0], redm[nb * 4 + 1]),
                         fmaxf(redm[nb * 4 + 2], redm[nb * 4 + 3]));
        uint32_t Ea[8], Eb[8];
#pragma unroll
        for (int nt = 0; nt < 8; nt++) {
            float* d = accr[mt][nt];
            Ea[nt] = ex2_h2(pack_h2((d[0] - ma) * L2E, (d[1] - ma) * L2E));
            Eb[nt] = ex2_h2(pack_h2((d[2] - mb) * L2E, (d[3] - mb) * L2E));
        }
        float sacc[4] = {};
#pragma unroll
        for (int q = 0; q < 4; q++) {
            uint32_t aF[4] = {Ea[2 * q], Eb[2 * q], Ea[2 * q + 1], Eb[2 * q + 1]};
            mma16(sacc, aF, ones2);
        }
        if (tg == 0) { reds[na * 4 + wn] = sacc[0]; reds[nb * 4 + wn] = sacc[2]; }
#pragma unroll
        for (int nt = 0; nt < 8; nt++) {
            int v = v0 + nt * 8 + 2 * tg;
            AsU[na * 132 + (v >> 1)] = Ea[nt];
            AsU[nb * 132 + (v >> 1)] = Eb[nt];
        }
    }
    __syncthreads();

    if (t < 64) {
        float s = reds[t * 4] + reds[t * 4 + 1] + reds[t * 4 + 2] + reds[t * 4 + 3];
        scS[t] = actS[t] / s;
    }
    __syncthreads();

    // ---- out GEMM (fp16): out[c][n] = VC @ route, M=128, N=64, K=256 -------
    const int wm2 = wid >> 1, wn2 = wid & 1;
    const int c0 = wm2 * 32, n0o = wn2 * 32;
    float acco[2][4][4] = {};
    {
        const uint32_t* vcp = g_vcf16 + ((size_t)(b * 16) * 8 + wm2 * 2) * 128 + lane * 4;
        uint4 curA[2], nxtA[2];
#pragma unroll
        for (int mt = 0; mt < 2; mt++) curA[mt] = *(const uint4*)(vcp + mt * 128);
        for (int v16 = 0; v16 < 16; v16++) {
            if (v16 < 15) {
                const uint32_t* p = vcp + (size_t)(v16 + 1) * 1024;
#pragma unroll
                for (int mt = 0; mt < 2; mt++) nxtA[mt] = *(const uint4*)(p + mt * 128);
            }
#pragma unroll
            for (int ntp = 0; ntp < 2; ntp++) {
                uint32_t bF[4];
                uint32_t adr = as_b + (uint32_t)((n0o + ntp * 16 + lhi * 8 + l7) * 528
                                                  + v16 * 32 + lr8 * 16);
                ldm_x4(bF, adr);
#pragma unroll
                for (int mt = 0; mt < 2; mt++) {
                    mma16(acco[mt][2 * ntp],     (const uint32_t*)&curA[mt], bF);
                    mma16(acco[mt][2 * ntp + 1], (const uint32_t*)&curA[mt], bF + 2);
                }
            }
#pragma unroll
            for (int mt = 0; mt < 2; mt++) curA[mt] = nxtA[mt];
        }
    }

#pragma unroll
    for (int mt = 0; mt < 2; mt++) {
#pragma unroll
        for (int nt = 0; nt < 4; nt++) {
            int r0 = c0 + mt * 16 + gr;
            int ln = n0o + (nt >> 1) * 16 + (nt & 1) * 8 + 2 * tg;
            int ng = n0g + ln;
            float sc0 = scS[ln], sc1 = scS[ln + 1];
            float* d = acco[mt][nt];
            if (ng < N_WRD) {
                float2 s0; s0.x = d[0] * sc0; s0.y = d[1] * sc1;
                float2 s1; s1.x = d[2] * sc0; s1.y = d[3] * sc1;
                *(float2*)&out[((size_t)b * CSZ + r0) * N_WRD + ng]     = s0;
                *(float2*)&out[((size_t)b * CSZ + r0 + 8) * N_WRD + ng] = s1;
            }
        }
    }
}

// ---------------- launch --------------------------------------------------
extern "C" void kernel_launch(void* const* d_in, const int* in_sizes, int n_in,
                              void* d_out, int out_size) {
    const float* view_cell = (const float*)d_in[0];
    const float* v         = (const float*)d_in[1];
    const float* w2c_w1    = (const float*)d_in[2];
    const float* w2c_b1    = (const float*)d_in[3];
    const float* w2c_w2    = (const float*)d_in[4];
    const float* w2c_b2    = (const float*)d_in[5];
    const float* fc1_w     = (const float*)d_in[6];
    const float* fc1_b     = (const float*)d_in[7];
    const float* fc2_w     = (const float*)d_in[8];
    const float* fc2_b     = (const float*)d_in[9];
    const float* fca_w     = (const float*)d_in[10];
    const float* fca_b     = (const float*)d_in[11];
    const float* fce_w     = (const float*)d_in[12];
    const float* fce_b     = (const float*)d_in[13];
    const float* vse_w1    = (const float*)d_in[14];
    const float* vse_b1    = (const float*)d_in[15];
    const float* vse_w2    = (const float*)d_in[16];
    const float* vse_b2    = (const float*)d_in[17];
    float* out = (float*)d_out;

    static bool attr_set = false;
    if (!attr_set) {
        cudaFuncSetAttribute(k_AB, cudaFuncAttributeMaxDynamicSharedMemorySize, KF_TOT * 4);
        attr_set = true;
    }

    k_setup<<<783, 256>>>(fc2_w, fce_w, fca_w, view_cell, v, w2c_w1, w2c_b1,
                          w2c_w2, w2c_b2, fc1_w, fc1_b,
                          vse_w1, vse_b1, vse_w2, vse_b2);
    dim3 gridF((N_WRD + 63) / 64, B_SZ);
    k_AB<<<gridF, 256, KF_TOT * 4>>>(fc2_b, fca_b, fce_b, out);
}